// round 8
// baseline (speedup 1.0000x reference)
#include <cuda_runtime.h>

// Problem constants
#define CTC_B 256
#define CTC_T 256
#define CTC_C 512
#define CTC_L 64
#define ROWE  66            // g_emit floats per row: 64 label probs + blank + pad
#define LOG2E 1.4426950408889634f
#define LN2   0.6931471805599453f
#define DPCH  8             // DP prefetch chunk (rows)
#define NCH   (CTC_T / DPCH)

__device__ float g_emit[(size_t)CTC_B * CTC_T * ROWE];   // softmax PROBS (~17 MB)
__device__ float g_nll[CTC_B];
__device__ unsigned int g_count = 0;

__device__ __forceinline__ float warpsum(float v) {
#pragma unroll
    for (int o = 16; o; o >>= 1) v += __shfl_xor_sync(0xffffffffu, v, o);
    return v;
}

// Kernel 1: per (b,t) row: softmax over C=512, write the 65 needed
// probabilities (64 label slots + blank) to g_emit. One warp per row.
__global__ void __launch_bounds__(256) lse_emit_kernel(
    const float* __restrict__ logits, const int* __restrict__ labels)
{
    __shared__ float srow[8][CTC_C];    // exp values
    __shared__ int   slab[CTC_L];
    const int w    = threadIdx.x >> 5;
    const int lane = threadIdx.x & 31;
    const int row_id = blockIdx.x * 8 + w;          // = b*T + t
    const int b = blockIdx.x >> 5;                  // 32 blocks per batch

    if (threadIdx.x < CTC_L) slab[threadIdx.x] = labels[b * CTC_L + threadIdx.x];

    const float4* row4 = (const float4*)(logits + (size_t)row_id * CTC_C);
    float4 v[4];
#pragma unroll
    for (int k = 0; k < 4; k++) v[k] = row4[k * 32 + lane];

    // Unshifted exp-sum (logits are O(1): no overflow risk)
    float s = 0.f;
#pragma unroll
    for (int k = 0; k < 4; k++) {
        const float e0 = exp2f(v[k].x * LOG2E);
        const float e1 = exp2f(v[k].y * LOG2E);
        const float e2 = exp2f(v[k].z * LOG2E);
        const float e3 = exp2f(v[k].w * LOG2E);
        const int i4 = (k * 32 + lane) * 4;
        srow[w][i4 + 0] = e0; srow[w][i4 + 1] = e1;
        srow[w][i4 + 2] = e2; srow[w][i4 + 3] = e3;
        s += e0 + e1 + e2 + e3;
    }
    s = warpsum(s);
    const float rcp = __frcp_rn(s);
    __syncthreads();                    // srow + slab visibility

    float* eout = g_emit + (size_t)row_id * ROWE;
    eout[lane]      = srow[w][slab[lane]]      * rcp;
    eout[32 + lane] = srow[w][slab[32 + lane]] * rcp;
    if (lane == 0)
        eout[CTC_L] = srow[w][CTC_C - 1] * rcp;      // blank = last class
}

// Kernel 2: CTC forward DP in DOUBLE-precision probability domain.
// One warp per batch element; lane l owns states s = 4l+j (j=0..3);
// lane 31 additionally s=128. Warp-UNIFORM power-of-2 rescale every 64
// steps (exact; ~2000-bit effective exponent window).
__global__ void __launch_bounds__(32) ctc_dp_kernel(
    const int* __restrict__ labels,
    const int* __restrict__ label_length,
    const int* __restrict__ logit_length,
    float* __restrict__ out)
{
    __shared__ int slab[CTC_L];
    const int b    = blockIdx.x;
    const int lane = threadIdx.x;

    slab[lane]      = labels[b * CTC_L + lane];
    slab[32 + lane] = labels[b * CTC_L + 32 + lane];
    __syncwarp();

    const int tl = logit_length[b];
    const int ll = label_length[b];
    const int tlm1 = tl - 1;

    // skip multipliers (odd states only): s=4l+1 sym=2l ; s=4l+3 sym=2l+1
    const double sk1 = ((4 * lane + 1) >= 3 && slab[2 * lane] != slab[2 * lane - 1]) ? 1.0 : 0.0;
    const double sk3 = (slab[2 * lane + 1] != slab[2 * lane]) ? 1.0 : 0.0;

    const float* ebase = g_emit + (size_t)b * CTC_T * ROWE;

    float2 e2A[DPCH], e2B[DPCH];
    float  ebA[DPCH], ebB[DPCH];

    auto load_chunk = [&](int c, float2* e2, float* eb) {
#pragma unroll
        for (int j = 0; j < DPCH; j++) {
            const float* r = ebase + (size_t)(c * DPCH + j) * ROWE;
            e2[j] = __ldg((const float2*)r + lane);   // probs of syms 2l, 2l+1
            eb[j] = __ldg(r + CTC_L);                 // blank prob
        }
    };

    double a0 = 0., a1 = 0., a2 = 0., a3 = 0., a4 = 0.;
    double s0 = 0., s1 = 0., s2 = 0., s3 = 0., s4 = 0.;
    int E = 0, sE = 0;      // warp-uniform exponent: true alpha = a * 2^E

    auto compute_chunk = [&](int c, const float2* e2, const float* eb) {
#pragma unroll
        for (int j = 0; j < DPCH; j++) {
            const int t = c * DPCH + j;
            const double ex  = (double)e2[j].x;
            const double ey  = (double)e2[j].y;
            const double ebd = (double)eb[j];
            if (t == 0) {
                a0 = (lane == 0) ? ebd : 0.;     // s=0 blank
                a1 = (lane == 0) ? ex  : 0.;     // s=1 label0
                a2 = 0.; a3 = 0.; a4 = 0.;
            } else {
                double am1 = __shfl_up_sync(0xffffffffu, a3, 1);  // alpha[4l-1]
                if (lane == 0) am1 = 0.;
                const double na0 = (a0 + am1)             * ebd;
                const double na1 = (a1 + a0 + sk1 * am1)  * ex;
                const double na2 = (a2 + a1)              * ebd;
                const double na3 = (a3 + a2 + sk3 * a1)   * ey;
                const double na4 = (a4 + a3)              * ebd;
                a0 = na0; a1 = na1; a2 = na2; a3 = na3; a4 = na4;
            }
            if (t == tlm1) { s0 = a0; s1 = a1; s2 = a2; s3 = a3; s4 = a4; sE = E; }

            if ((t & 63) == 63) {
                // warp-uniform exact power-of-2 rescale
                double m = fmax(fmax(fmax(a0, a1), fmax(a2, a3)), a4);
#pragma unroll
                for (int o = 16; o; o >>= 1)
                    m = fmax(m, __shfl_xor_sync(0xffffffffu, m, o));
                const int ex2 = ((__double2hiint(m) >> 20) & 0x7ff) - 1023;
                const double r = __hiloint2double((1023 - ex2) << 20, 0); // 2^-ex2
                a0 *= r; a1 *= r; a2 *= r; a3 *= r; a4 *= r;
                E += ex2;
            }
        }
    };

    load_chunk(0, e2A, ebA);
#pragma unroll 2
    for (int c = 0; c < NCH; c++) {
        if (c & 1) {
            if (c + 1 < NCH) load_chunk(c + 1, e2A, ebA);
            compute_chunk(c, e2B, ebB);
        } else {
            if (c + 1 < NCH) load_chunk(c + 1, e2B, ebB);
            compute_chunk(c, e2A, ebA);
        }
    }

    // -------- finalize --------
    const int se = 2 * ll;              // final blank state
    const int sm = se - 1;
    const int ie = (se >> 2) & 31;
    const int im = (sm >> 2) & 31;
    const double t0 = __shfl_sync(0xffffffffu, s0, ie);
    const double t1 = __shfl_sync(0xffffffffu, s1, ie);
    const double t2 = __shfl_sync(0xffffffffu, s2, ie);
    const double t3 = __shfl_sync(0xffffffffu, s3, ie);
    const double t4 = __shfl_sync(0xffffffffu, s4, 31);
    const double u0 = __shfl_sync(0xffffffffu, s0, im);
    const double u1 = __shfl_sync(0xffffffffu, s1, im);
    const double u2 = __shfl_sync(0xffffffffu, s2, im);
    const double u3 = __shfl_sync(0xffffffffu, s3, im);

    unsigned done = 0;
    if (lane == 0) {
        const int je = se & 3;
        const double v_end = (se >= 128) ? t4
                           : (je == 0 ? t0 : je == 1 ? t1 : je == 2 ? t2 : t3);
        const int jm = sm & 3;
        const double v_m1 = (jm == 0 ? u0 : jm == 1 ? u1 : jm == 2 ? u2 : u3);
        double p = v_end + v_m1;
        p = fmax(p, 4.9e-324);          // guard (end states always reachable)
        // log2(p) + sE, via exponent/mantissa split
        const int hi = __double2hiint(p);
        const int pe = ((hi >> 20) & 0x7ff) - 1023;
        const double mant = __hiloint2double((hi & 0x800FFFFF) | (1023 << 20),
                                             __double2loint(p));   // in [1,2)
        const float l2 = __log2f((float)mant) + (float)(pe + sE);
        g_nll[b] = -LN2 * l2;
        __threadfence();
        done = (atomicAdd(&g_count, 1u) == CTC_B - 1) ? 1u : 0u;
    }
    done = __shfl_sync(0xffffffffu, done, 0);
    if (done) {
        // last-finishing block: deterministic fixed-tree mean
        float s = 0.f;
#pragma unroll
        for (int i = 0; i < CTC_B / 32; i++)
            s += __ldcg(&g_nll[i * 32 + lane]);
        s = warpsum(s);
        if (lane == 0) {
            out[0] = s * (1.0f / CTC_B);
            g_count = 0;                 // reset for next graph replay
        }
    }
}

extern "C" void kernel_launch(void* const* d_in, const int* in_sizes, int n_in,
                              void* d_out, int out_size)
{
    const float* logits       = (const float*)d_in[0];
    const int*   labels       = (const int*)d_in[1];
    const int*   label_length = (const int*)d_in[2];
    const int*   logit_length = (const int*)d_in[3];

    lse_emit_kernel<<<(CTC_B * CTC_T) / 8, 256>>>(logits, labels);
    ctc_dp_kernel<<<CTC_B, 32>>>(labels, label_length, logit_length, (float*)d_out);
    (void)in_sizes; (void)n_in; (void)out_size;
}

// round 9
// speedup vs baseline: 3.2628x; 3.2628x over previous
#include <cuda_runtime.h>

// Problem constants
#define CTC_B 256
#define CTC_T 256
#define CTC_C 512
#define CTC_L 64
#define ROWE  66            // g_emit floats per row: 64 label probs + blank + pad
#define LOG2E 1.4426950408889634f
#define LN2   0.6931471805599453f
#define DPCH  8             // DP prefetch chunk (rows)
#define NCH   (CTC_T / DPCH)
#define ESENT (-(1 << 28))  // exponent sentinel for massless lanes

__device__ float g_emit[(size_t)CTC_B * CTC_T * ROWE];   // softmax PROBS (~17 MB)
__device__ float g_nll[CTC_B];
__device__ unsigned int g_count = 0;

__device__ __forceinline__ float warpsum(float v) {
#pragma unroll
    for (int o = 16; o; o >>= 1) v += __shfl_xor_sync(0xffffffffu, v, o);
    return v;
}

// logaddexp in log2 domain (finalize only)
__device__ __forceinline__ float lae2_2(float x, float y) {
    float m = fmaxf(x, y);
    float d = fminf(x, y) - m;
    return m + __log2f(1.0f + exp2f(d));
}

// Kernel 1 (validated in R8): per (b,t) row softmax over C=512, write 65
// needed probabilities (64 label slots + blank). One warp per row.
__global__ void __launch_bounds__(256) lse_emit_kernel(
    const float* __restrict__ logits, const int* __restrict__ labels)
{
    __shared__ float srow[8][CTC_C];
    __shared__ int   slab[CTC_L];
    const int w    = threadIdx.x >> 5;
    const int lane = threadIdx.x & 31;
    const int row_id = blockIdx.x * 8 + w;          // = b*T + t
    const int b = blockIdx.x >> 5;                  // 32 blocks per batch

    if (threadIdx.x < CTC_L) slab[threadIdx.x] = labels[b * CTC_L + threadIdx.x];

    const float4* row4 = (const float4*)(logits + (size_t)row_id * CTC_C);
    float4 v[4];
#pragma unroll
    for (int k = 0; k < 4; k++) v[k] = row4[k * 32 + lane];

    float s = 0.f;
#pragma unroll
    for (int k = 0; k < 4; k++) {
        const float e0 = exp2f(v[k].x * LOG2E);
        const float e1 = exp2f(v[k].y * LOG2E);
        const float e2 = exp2f(v[k].z * LOG2E);
        const float e3 = exp2f(v[k].w * LOG2E);
        const int i4 = (k * 32 + lane) * 4;
        srow[w][i4 + 0] = e0; srow[w][i4 + 1] = e1;
        srow[w][i4 + 2] = e2; srow[w][i4 + 3] = e3;
        s += e0 + e1 + e2 + e3;
    }
    s = warpsum(s);
    const float rcp = __frcp_rn(s);
    __syncthreads();

    float* eout = g_emit + (size_t)row_id * ROWE;
    eout[lane]      = srow[w][slab[lane]]      * rcp;
    eout[32 + lane] = srow[w][slab[32 + lane]] * rcp;
    if (lane == 0)
        eout[CTC_L] = srow[w][CTC_C - 1] * rcp;      // blank = last class
}

// Kernel 2: CTC forward DP, fp32 probability domain with PER-LANE exponent
// tracking (true alpha = a * 2^E). Massless lanes hold E = ESENT so they
// never dominate the exponent alignment (R6 bug fix). One warp per batch;
// lane l owns states s = 4l+j (j=0..3); lane 31 additionally s=128.
__global__ void __launch_bounds__(32) ctc_dp_kernel(
    const int* __restrict__ labels,
    const int* __restrict__ label_length,
    const int* __restrict__ logit_length,
    float* __restrict__ out)
{
    __shared__ int slab[CTC_L];
    const int b    = blockIdx.x;
    const int lane = threadIdx.x;

    slab[lane]      = labels[b * CTC_L + lane];
    slab[32 + lane] = labels[b * CTC_L + 32 + lane];
    __syncwarp();

    const int tl = logit_length[b];
    const int ll = label_length[b];
    const int tlm1 = tl - 1;

    // skip multipliers (odd states only): s=4l+1 sym=2l ; s=4l+3 sym=2l+1
    const float sk1 = ((4 * lane + 1) >= 3 && slab[2 * lane] != slab[2 * lane - 1]) ? 1.f : 0.f;
    const float sk3 = (slab[2 * lane + 1] != slab[2 * lane]) ? 1.f : 0.f;

    const float* ebase = g_emit + (size_t)b * CTC_T * ROWE;

    float2 e2A[DPCH], e2B[DPCH];
    float  ebA[DPCH], ebB[DPCH];

    auto load_chunk = [&](int c, float2* e2, float* eb) {
#pragma unroll
        for (int j = 0; j < DPCH; j++) {
            const float* r = ebase + (size_t)(c * DPCH + j) * ROWE;
            e2[j] = __ldg((const float2*)r + lane);   // probs of syms 2l, 2l+1
            eb[j] = __ldg(r + CTC_L);                 // blank prob
        }
    };

    float a0 = 0.f, a1 = 0.f, a2 = 0.f, a3 = 0.f, a4 = 0.f;
    float s0 = 0.f, s1 = 0.f, s2 = 0.f, s3 = 0.f, s4 = 0.f;
    int E = ESENT, sE = ESENT;

    auto compute_chunk = [&](int c, const float2* e2, const float* eb) {
#pragma unroll
        for (int j = 0; j < DPCH; j++) {
            const int t = c * DPCH + j;
            if (t == 0) {
                a0 = (lane == 0) ? eb[0]    : 0.f;    // s=0 blank
                a1 = (lane == 0) ? e2[0].x  : 0.f;    // s=1 label0
                a2 = 0.f; a3 = 0.f; a4 = 0.f;
                E  = (lane == 0) ? 0 : ESENT;
            } else {
                float am1 = __shfl_up_sync(0xffffffffu, a3, 1);  // alpha[4l-1]
                int   Ep  = __shfl_up_sync(0xffffffffu, E,  1);
                if (lane == 0) am1 = 0.f;             // (Ep==E for lane 0)
                // align both sides to En = max(E, Ep); exact 2^d factors
                const int   En = max(E, Ep);
                const float f1 = __int_as_float(max(127 + (E  - En), 0) << 23);
                const float f2 = __int_as_float(max(127 + (Ep - En), 0) << 23);
                am1 *= f2;
                a0 *= f1; a1 *= f1; a2 *= f1; a3 *= f1; a4 *= f1;
                E = En;

                const float na0 = (a0 + am1)              * eb[j];
                const float na1 = fmaf(sk1, am1, a1 + a0) * e2[j].x;
                const float na2 = (a2 + a1)               * eb[j];
                const float na3 = fmaf(sk3, a1, a3 + a2)  * e2[j].y;
                const float na4 = (a4 + a3)               * eb[j];
                a0 = na0; a1 = na1; a2 = na2; a3 = na3; a4 = na4;
            }
            if (t == tlm1) { s0 = a0; s1 = a1; s2 = a2; s3 = a3; s4 = a4; sE = E; }

            if (t & 1) {
                // per-lane renorm every 2 steps; massless lanes -> sentinel
                const float m = fmaxf(fmaxf(fmaxf(a0, a1), fmaxf(a2, a3)), a4);
                if (m > 0.f) {
                    const int ex = (__float_as_int(m) >> 23) - 127;
                    const float r = __int_as_float((127 - ex) << 23);   // 2^-ex
                    a0 *= r; a1 *= r; a2 *= r; a3 *= r; a4 *= r;
                    E += ex;
                } else {
                    E = ESENT;
                }
            }
        }
    };

    load_chunk(0, e2A, ebA);
#pragma unroll 2
    for (int c = 0; c < NCH; c++) {
        if (c & 1) {
            if (c + 1 < NCH) load_chunk(c + 1, e2A, ebA);
            compute_chunk(c, e2B, ebB);
        } else {
            if (c + 1 < NCH) load_chunk(c + 1, e2B, ebB);
            compute_chunk(c, e2A, ebA);
        }
    }

    // -------- finalize --------
    const int se = 2 * ll;              // final blank state
    const int sm = se - 1;
    const int ie = (se >> 2) & 31;
    const int im = (sm >> 2) & 31;
    const float t0 = __shfl_sync(0xffffffffu, s0, ie);
    const float t1 = __shfl_sync(0xffffffffu, s1, ie);
    const float t2 = __shfl_sync(0xffffffffu, s2, ie);
    const float t3 = __shfl_sync(0xffffffffu, s3, ie);
    const float t4 = __shfl_sync(0xffffffffu, s4, 31);
    const int   Ee0 = __shfl_sync(0xffffffffu, sE, ie);
    const int   Ee4 = __shfl_sync(0xffffffffu, sE, 31);
    const float u0 = __shfl_sync(0xffffffffu, s0, im);
    const float u1 = __shfl_sync(0xffffffffu, s1, im);
    const float u2 = __shfl_sync(0xffffffffu, s2, im);
    const float u3 = __shfl_sync(0xffffffffu, s3, im);
    const int   Em0 = __shfl_sync(0xffffffffu, sE, im);

    unsigned done = 0;
    if (lane == 0) {
        const int je = se & 3;
        const float v_end = (se >= 128) ? t4
                          : (je == 0 ? t0 : je == 1 ? t1 : je == 2 ? t2 : t3);
        const int   E_end = (se >= 128) ? Ee4 : Ee0;
        const int jm = sm & 3;
        const float v_m1 = (jm == 0 ? u0 : jm == 1 ? u1 : jm == 2 ? u2 : u3);
        // log2(alpha) = log2(mantissa) + E
        const float le = __log2f(fmaxf(v_end, 1e-45f)) + (float)E_end;
        const float lm = __log2f(fmaxf(v_m1, 1e-45f)) + (float)Em0;
        g_nll[b] = -LN2 * lae2_2(le, lm);
        __threadfence();
        done = (atomicAdd(&g_count, 1u) == CTC_B - 1) ? 1u : 0u;
    }
    done = __shfl_sync(0xffffffffu, done, 0);
    if (done) {
        // last-finishing block: deterministic fixed-tree mean
        float s = 0.f;
#pragma unroll
        for (int i = 0; i < CTC_B / 32; i++)
            s += __ldcg(&g_nll[i * 32 + lane]);
        s = warpsum(s);
        if (lane == 0) {
            out[0] = s * (1.0f / CTC_B);
            g_count = 0;                 // reset for next graph replay
        }
    }
}

extern "C" void kernel_launch(void* const* d_in, const int* in_sizes, int n_in,
                              void* d_out, int out_size)
{
    const float* logits       = (const float*)d_in[0];
    const int*   labels       = (const int*)d_in[1];
    const int*   label_length = (const int*)d_in[2];
    const int*   logit_length = (const int*)d_in[3];

    lse_emit_kernel<<<(CTC_B * CTC_T) / 8, 256>>>(logits, labels);
    ctc_dp_kernel<<<CTC_B, 32>>>(labels, label_length, logit_length, (float*)d_out);
    (void)in_sizes; (void)n_in; (void)out_size;
}

// round 10
// speedup vs baseline: 3.7338x; 1.1444x over previous
#include <cuda_runtime.h>

// Problem constants
#define CTC_B 256
#define CTC_T 256
#define CTC_C 512
#define CTC_L 64
#define ROWE  66            // g_emit floats per row: 64 label probs + blank + pad
#define LOG2E 1.4426950408889634f
#define LN2   0.6931471805599453f
#define DPCH  8             // DP prefetch chunk (rows)
#define ESENT (-(1 << 28))  // exponent sentinel for massless lanes

__device__ float g_emit[(size_t)CTC_B * CTC_T * ROWE];   // softmax PROBS (~17 MB)
__device__ float g_nll[CTC_B];
__device__ unsigned int g_count = 0;

__device__ __forceinline__ float warpsum(float v) {
#pragma unroll
    for (int o = 16; o; o >>= 1) v += __shfl_xor_sync(0xffffffffu, v, o);
    return v;
}
__device__ __forceinline__ float warpmaxf(float v) {
#pragma unroll
    for (int o = 16; o; o >>= 1) v = fmaxf(v, __shfl_xor_sync(0xffffffffu, v, o));
    return v;
}

// Kernel 1 (validated R8/R9): per (b,t) row softmax over C=512, write 65
// needed probabilities (64 label slots + blank). One warp per row.
__global__ void __launch_bounds__(256) lse_emit_kernel(
    const float* __restrict__ logits, const int* __restrict__ labels)
{
    __shared__ float srow[8][CTC_C];
    __shared__ int   slab[CTC_L];
    const int w    = threadIdx.x >> 5;
    const int lane = threadIdx.x & 31;
    const int row_id = blockIdx.x * 8 + w;          // = b*T + t
    const int b = blockIdx.x >> 5;                  // 32 blocks per batch

    if (threadIdx.x < CTC_L) slab[threadIdx.x] = labels[b * CTC_L + threadIdx.x];

    const float4* row4 = (const float4*)(logits + (size_t)row_id * CTC_C);
    float4 v[4];
#pragma unroll
    for (int k = 0; k < 4; k++) v[k] = row4[k * 32 + lane];

    float s = 0.f;
#pragma unroll
    for (int k = 0; k < 4; k++) {
        const float e0 = exp2f(v[k].x * LOG2E);
        const float e1 = exp2f(v[k].y * LOG2E);
        const float e2 = exp2f(v[k].z * LOG2E);
        const float e3 = exp2f(v[k].w * LOG2E);
        const int i4 = (k * 32 + lane) * 4;
        srow[w][i4 + 0] = e0; srow[w][i4 + 1] = e1;
        srow[w][i4 + 2] = e2; srow[w][i4 + 3] = e3;
        s += e0 + e1 + e2 + e3;
    }
    s = warpsum(s);
    const float rcp = __frcp_rn(s);
    __syncthreads();

    float* eout = g_emit + (size_t)row_id * ROWE;
    eout[lane]      = srow[w][slab[lane]]      * rcp;
    eout[32 + lane] = srow[w][slab[32 + lane]] * rcp;
    if (lane == 0)
        eout[CTC_L] = srow[w][CTC_C - 1] * rcp;      // blank = last class
}

// Kernel 2: bidirectional CTC DP, fp32 probability domain with per-lane
// exponents (R9-validated scheme). One warp per batch. Forward alpha over
// t = 0..tm-1 and backward beta over t = tl-1..tm run INTERLEAVED in the
// same warp (independent chains fill each other's stall slots).
// p = sum_s alpha_{tm-1}(s) * beta_{tm-1}(s).
__global__ void __launch_bounds__(32) ctc_dp_kernel(
    const int* __restrict__ labels,
    const int* __restrict__ label_length,
    const int* __restrict__ logit_length,
    float* __restrict__ out)
{
    __shared__ int slab[CTC_L];
    const int b    = blockIdx.x;
    const int lane = threadIdx.x;

    slab[lane]      = labels[b * CTC_L + lane];
    slab[32 + lane] = labels[b * CTC_L + 32 + lane];
    __syncwarp();

    const int tl = logit_length[b];          // == 256 for this problem
    const int ll = label_length[b];
    const int tm = tl >> 1;                  // forward covers [0, tm)
    const int NIT = tm / DPCH;               // chunks per direction

    // skip flags: sk1 = skip into s=4l+1 (labels 2l vs 2l-1);
    //             sk3 = skip into s=4l+3 (labels 2l+1 vs 2l)
    const float sk1 = ((4 * lane + 1) >= 3 && slab[2 * lane] != slab[2 * lane - 1]) ? 1.f : 0.f;
    const float sk3 = (slab[2 * lane + 1] != slab[2 * lane]) ? 1.f : 0.f;

    const float* ebase = g_emit + (size_t)b * CTC_T * ROWE;

    // emission buffers: fwd rows ascend from 0; bwd rows descend from tl-1
    float2 fe2A[DPCH], fe2B[DPCH], be2A[DPCH], be2B[DPCH];
    float  febA[DPCH], febB[DPCH], bebA[DPCH], bebB[DPCH];

    auto load_f = [&](int k, float2* e2, float* eb) {
#pragma unroll
        for (int j = 0; j < DPCH; j++) {
            const float* r = ebase + (size_t)(k * DPCH + j) * ROWE;
            e2[j] = __ldg((const float2*)r + lane);
            eb[j] = __ldg(r + CTC_L);
        }
    };
    auto load_b = [&](int k, float2* e2, float* eb) {
#pragma unroll
        for (int j = 0; j < DPCH; j++) {
            const float* r = ebase + (size_t)(tl - 1 - (k * DPCH + j)) * ROWE;
            e2[j] = __ldg((const float2*)r + lane);
            eb[j] = __ldg(r + CTC_L);
        }
    };

    // forward state (alpha)
    float a0 = 0.f, a1 = 0.f, a2 = 0.f, a3 = 0.f, a4 = 0.f;
    int EA = ESENT;
    // backward state (beta): init at t = tl-1 as indicator of final states
    const int se = 2 * ll, sm = se - 1;
    float b0, b1, b2, b3, b4;
    int EB;
    {
        const int s0i = 4 * lane;
        b0 = (s0i == se || s0i == sm) ? 1.f : 0.f;
        b1 = (s0i + 1 == se || s0i + 1 == sm) ? 1.f : 0.f;
        b2 = (s0i + 2 == se || s0i + 2 == sm) ? 1.f : 0.f;
        b3 = (s0i + 3 == se || s0i + 3 == sm) ? 1.f : 0.f;
        b4 = (lane == 31 && se == 128) ? 1.f : 0.f;
        EB = (b0 + b1 + b2 + b3 + b4 > 0.f) ? 0 : ESENT;
    }

    auto fwd_step = [&](bool first, const float2 e2, const float eb) {
        if (first) {
            a0 = (lane == 0) ? eb   : 0.f;
            a1 = (lane == 0) ? e2.x : 0.f;
            a2 = 0.f; a3 = 0.f; a4 = 0.f;
            EA = (lane == 0) ? 0 : ESENT;
        } else {
            float am1 = __shfl_up_sync(0xffffffffu, a3, 1);
            int   Ep  = __shfl_up_sync(0xffffffffu, EA, 1);
            if (lane == 0) am1 = 0.f;
            const int   En = max(EA, Ep);
            const float f1 = __int_as_float(max(127 + (EA - En), 0) << 23);
            const float f2 = __int_as_float(max(127 + (Ep - En), 0) << 23);
            am1 *= f2;
            a0 *= f1; a1 *= f1; a2 *= f1; a3 *= f1; a4 *= f1;
            EA = En;
            const float na0 = (a0 + am1)              * eb;
            const float na1 = fmaf(sk1, am1, a1 + a0) * e2.x;
            const float na2 = (a2 + a1)               * eb;
            const float na3 = fmaf(sk3, a1, a3 + a2)  * e2.y;
            const float na4 = (a4 + a3)               * eb;
            a0 = na0; a1 = na1; a2 = na2; a3 = na3; a4 = na4;
        }
    };
    auto fwd_renorm = [&]() {
        const float m = fmaxf(fmaxf(fmaxf(a0, a1), fmaxf(a2, a3)), a4);
        if (m > 0.f) {
            const int ex = (__float_as_int(m) >> 23) - 127;
            const float r = __int_as_float((127 - ex) << 23);
            a0 *= r; a1 *= r; a2 *= r; a3 *= r; a4 *= r;
            EA += ex;
        } else EA = ESENT;
    };

    auto bwd_step = [&](const float2 e2, const float eb) {
        // products with this timestep's emissions
        const float p1  = e2.x * b1;     // succ state 4l+1
        const float p3  = e2.y * b3;     // succ state 4l+3
        const float pb0 = eb * b0;
        const float pb2 = eb * b2;
        const float pb4 = eb * b4;       // lane31: state 128
        // bundle exported to lane l-1 (successors of its s=4l-1):
        //   blank 4l (pb0) + skip into 4l+1 (sk1 * p1)
        const float z = fmaf(sk1, p1, pb0);
        float zin = __shfl_down_sync(0xffffffffu, z, 1);
        int   EpB = __shfl_down_sync(0xffffffffu, EB, 1);
        if (lane == 31) { zin = pb4; EpB = EB; }   // s=127 -> s=128 (own)
        const int   En = max(EB, EpB);
        const float f1 = __int_as_float(max(127 + (EB  - En), 0) << 23);
        const float f2 = __int_as_float(max(127 + (EpB - En), 0) << 23);
        const float nb0 = (pb0 + p1)              * f1;
        const float nb1 = fmaf(sk3, p3, p1 + pb2) * f1;
        const float nb2 = (pb2 + p3)              * f1;
        const float nb3 = fmaf(zin, f2, p3 * f1);
        const float nb4 = pb4 * f1;
        b0 = nb0; b1 = nb1; b2 = nb2; b3 = nb3; b4 = nb4;
        EB = En;
    };
    auto bwd_renorm = [&]() {
        const float m = fmaxf(fmaxf(fmaxf(b0, b1), fmaxf(b2, b3)), b4);
        if (m > 0.f) {
            const int ex = (__float_as_int(m) >> 23) - 127;
            const float r = __int_as_float((127 - ex) << 23);
            b0 *= r; b1 *= r; b2 *= r; b3 *= r; b4 *= r;
            EB += ex;
        } else EB = ESENT;
    };

    load_f(0, fe2A, febA);
    load_b(0, be2A, bebA);
#pragma unroll 2
    for (int k = 0; k < NIT; k++) {
        const bool useA = !(k & 1);
        float2* fe2 = useA ? fe2A : fe2B;  float* feb = useA ? febA : febB;
        float2* be2 = useA ? be2A : be2B;  float* beb = useA ? bebA : bebB;
        if (k + 1 < NIT) {
            load_f(k + 1, useA ? fe2B : fe2A, useA ? febB : febA);
            load_b(k + 1, useA ? be2B : be2A, useA ? bebB : bebA);
        }
#pragma unroll
        for (int j = 0; j < DPCH; j++) {
            fwd_step(k == 0 && j == 0, fe2[j], feb[j]);
            bwd_step(be2[j], beb[j]);
            if (j & 1) { fwd_renorm(); bwd_renorm(); }
        }
    }

    // -------- combine: p = sum_s alpha_{tm-1}(s) * beta_{tm-1}(s) --------
    float dot = a0 * b0 + a1 * b1 + a2 * b2 + a3 * b3;
    if (lane == 31) dot += a4 * b4;
    float l2d = (dot > 0.f) ? (__log2f(dot) + (float)(EA + EB)) : -1e30f;
    const float m = warpmaxf(l2d);
    const float ssum = warpsum(exp2f(l2d - m));

    unsigned done = 0;
    if (lane == 0) {
        g_nll[b] = -LN2 * (m + __log2f(ssum));
        __threadfence();
        done = (atomicAdd(&g_count, 1u) == CTC_B - 1) ? 1u : 0u;
    }
    done = __shfl_sync(0xffffffffu, done, 0);
    if (done) {
        // last-finishing block: deterministic fixed-tree mean
        float s = 0.f;
#pragma unroll
        for (int i = 0; i < CTC_B / 32; i++)
            s += __ldcg(&g_nll[i * 32 + lane]);
        s = warpsum(s);
        if (lane == 0) {
            out[0] = s * (1.0f / CTC_B);
            g_count = 0;                 // reset for next graph replay
        }
    }
}

extern "C" void kernel_launch(void* const* d_in, const int* in_sizes, int n_in,
                              void* d_out, int out_size)
{
    const float* logits       = (const float*)d_in[0];
    const int*   labels       = (const int*)d_in[1];
    const int*   label_length = (const int*)d_in[2];
    const int*   logit_length = (const int*)d_in[3];

    lse_emit_kernel<<<(CTC_B * CTC_T) / 8, 256>>>(logits, labels);
    ctc_dp_kernel<<<CTC_B, 32>>>(labels, label_length, logit_length, (float*)d_out);
    (void)in_sizes; (void)n_in; (void)out_size;
}